// round 3
// baseline (speedup 1.0000x reference)
#include <cuda_runtime.h>
#include <cstdint>
#include <cstddef>

// LSTM encoder: B=128, T=2048, I=64, H=128
// out[0 : B*H) = h_last ; out[B*H : ...) = encoded [B,T,H]
constexpr int B = 128;
constexpr int T = 2048;
constexpr int I = 64;
constexpr int H = 128;
constexpr int G = 4 * H;            // 512 gates
constexpr int KREG = 104;           // W_hh k-values in registers per gate
constexpr int KSM  = H - KREG;      // 24 in smem
constexpr int NP   = KREG / 2;      // 52 f32x2 pairs per gate
constexpr int NQR  = KREG / 4;      // 26 h-quads for register part
constexpr int NQ_SM = KSM / 4;      // 6 smem quads

// x_proj scratch, padded by 2*G for branch-free prefetch overread
__device__ float g_xp[(size_t)B * T * G + 2 * G];

__device__ __forceinline__ void fma2(unsigned long long& d,
                                     unsigned long long a,
                                     unsigned long long b) {
    asm("fma.rn.f32x2 %0, %1, %2, %0;" : "+l"(d) : "l"(a), "l"(b));
}
__device__ __forceinline__ float pair_sum(unsigned long long v) {
    return __uint_as_float((unsigned)v) + __uint_as_float((unsigned)(v >> 32));
}
__device__ __forceinline__ float sig_f(float x) {
    return __fdividef(1.f, 1.f + __expf(-x));
}
__device__ __forceinline__ float tanh_f(float x) {
    return 1.f - 2.f * __fdividef(1.f, 1.f + __expf(2.f * x));
}

// ---------------------------------------------------------------------------
// x_proj: 256 threads, 32 rows/CTA, thread t computes gates t and t+256.
// ---------------------------------------------------------------------------
__global__ void __launch_bounds__(256) xproj_kernel(
    const float* __restrict__ in,     // [B*T, I]
    const float* __restrict__ Wih,    // [G, I]
    const float* __restrict__ bih,
    const float* __restrict__ bhh)
{
    __shared__ float in_s[32 * I];
    const int t = threadIdx.x;
    const size_t row0 = (size_t)blockIdx.x * 32;

    {
        const float4* src = (const float4*)(in + row0 * I);
        float4* dst = (float4*)in_s;
        dst[t]       = src[t];
        dst[t + 256] = src[t + 256];
    }

    const int gA = t, gB = t + 256;
    unsigned long long wA[32], wB[32];
    {
        const unsigned long long* ra = (const unsigned long long*)(Wih + (size_t)gA * I);
        const unsigned long long* rb = (const unsigned long long*)(Wih + (size_t)gB * I);
#pragma unroll
        for (int i = 0; i < 32; i++) { wA[i] = ra[i]; wB[i] = rb[i]; }
    }
    const float biasA = bih[gA] + bhh[gA];
    const float biasB = bih[gB] + bhh[gB];
    __syncthreads();

    float* outp = g_xp + row0 * G + gA;
#pragma unroll 2
    for (int r = 0; r < 32; r++) {
        const ulonglong2* ip = (const ulonglong2*)(in_s + r * I);
        unsigned long long a0 = 0ull, a1 = 0ull, b0 = 0ull, b1 = 0ull;
#pragma unroll
        for (int q = 0; q < 16; q++) {
            ulonglong2 iv = ip[q];
            fma2(a0, wA[2 * q],     iv.x);
            fma2(a1, wA[2 * q + 1], iv.y);
            fma2(b0, wB[2 * q],     iv.x);
            fma2(b1, wB[2 * q + 1], iv.y);
        }
        outp[(size_t)r * G]       = pair_sum(a0) + pair_sum(a1) + biasA;
        outp[(size_t)r * G + 256] = pair_sum(b0) + pair_sum(b1) + biasB;
    }
}

// ---------------------------------------------------------------------------
// Recurrence: 1 CTA per batch row, 256 threads.
// Half A (tid<128, j=tid): gates i_j (row j), f_j (row j+128), owns c_j.
// Half B (tid>=128, j=tid-128): gates g_j (row j+256), o_j (row j+384).
// Both halves activate their own gates pre-barrier; B passes (tanh g, sig o)
// as one float2; A finishes the cell update. Two barriers/step.
// ---------------------------------------------------------------------------
__global__ void __launch_bounds__(256, 1) lstm_kernel(
    const float* __restrict__ h0,
    const float* __restrict__ c0,
    const float* __restrict__ Whh,   // [G, H]
    float* __restrict__ out)
{
    extern __shared__ float smem[];
    ulonglong2* Ws2  = (ulonglong2*)smem;              // [NQ_SM][G] quads, 48 KB
    float*      h_s  = smem + NQ_SM * G * 4;           // 128 floats
    float2*     ex_s = (float2*)(h_s + H);             // 128 float2

    const int tid  = threadIdx.x;
    const int half = tid >> 7;          // 0 = A, 1 = B
    const int j    = tid & 127;
    const int g0   = (half << 8) + j;   // i-row (A) / g-row (B)
    const int g1   = g0 + 128;          // f-row (A) / o-row (B)
    const int b    = blockIdx.x;

    {   // smem weight slice (k in [KREG,128)), k-major quads
        const ulonglong2* r0 = (const ulonglong2*)(Whh + (size_t)g0 * H + KREG);
        const ulonglong2* r1 = (const ulonglong2*)(Whh + (size_t)g1 * H + KREG);
#pragma unroll
        for (int q = 0; q < NQ_SM; q++) {
            Ws2[q * G + g0] = r0[q];
            Ws2[q * G + g1] = r1[q];
        }
    }

    unsigned long long w0[NP], w1[NP];
    {
        const unsigned long long* r0 = (const unsigned long long*)(Whh + (size_t)g0 * H);
        const unsigned long long* r1 = (const unsigned long long*)(Whh + (size_t)g1 * H);
#pragma unroll
        for (int i = 0; i < NP; i++) { w0[i] = r0[i]; w1[i] = r1[i]; }
    }

    float c = 0.f, hn_last = 0.f;
    if (half == 0) {
        c = c0[b * H + j];
        h_s[j] = h0[b * H + j];
    }

    const float* xp = g_xp + (size_t)b * T * G + g0;   // g1 stream = xp + 128
    float xc0 = xp[0],     xc1 = xp[128];
    float xn0 = xp[G],     xn1 = xp[G + 128];
    const float* xf = xp + 2 * G;                      // padded overread OK

    __syncthreads();

    float* enc = out + (size_t)B * H + (size_t)b * T * H;

    for (int t = 0; t < T; t++) {
        float xf0 = xf[0], xf1 = xf[128];
        xf += G;

        unsigned long long a0 = 0ull, a1 = 0ull, c0a = 0ull, c1a = 0ull;
        const ulonglong2* h2 = (const ulonglong2*)h_s;

#pragma unroll
        for (int q = 0; q < NQR; q++) {               // k in [0,104)
            ulonglong2 hv = h2[q];
            fma2(a0,  w0[2 * q],     hv.x);
            fma2(a1,  w0[2 * q + 1], hv.y);
            fma2(c0a, w1[2 * q],     hv.x);
            fma2(c1a, w1[2 * q + 1], hv.y);
        }
#pragma unroll
        for (int q = 0; q < NQ_SM; q++) {             // k in [104,128)
            ulonglong2 hv = h2[NQR + q];
            ulonglong2 wa = Ws2[q * G + g0];
            ulonglong2 wb = Ws2[q * G + g1];
            fma2(a0,  wa.x, hv.x);
            fma2(a1,  wa.y, hv.y);
            fma2(c0a, wb.x, hv.x);
            fma2(c1a, wb.y, hv.y);
        }

        float p0 = pair_sum(a0)  + pair_sum(a1)  + xc0;
        float p1 = pair_sum(c0a) + pair_sum(c1a) + xc1;
        xc0 = xn0; xn0 = xf0;
        xc1 = xn1; xn1 = xf1;

        // local activations (warp-uniform branch, no barrier inside)
        float v1 = sig_f(p1);            // A: sig(f) ; B: sig(o)
        float v0;
        if (half) v0 = tanh_f(p0);       // B: tanh(g)
        else      v0 = sig_f(p0);        // A: sig(i)

        if (half) ex_s[j] = make_float2(v0, v1);
        __syncthreads();

        if (!half) {
            float2 go = ex_s[j];                 // (tanh g, sig o)
            c = v1 * c + v0 * go.x;              // f*c + i*g
            float hn = go.y * tanh_f(c);
            h_s[j] = hn;
            enc[(size_t)t * H + j] = hn;
            hn_last = hn;
        }
        __syncthreads();
    }

    if (half == 0) out[b * H + j] = hn_last;
}

// ---------------------------------------------------------------------------
extern "C" void kernel_launch(void* const* d_in, const int* in_sizes, int n_in,
                              void* d_out, int out_size) {
    const float* input = (const float*)d_in[0];
    const float* h0    = (const float*)d_in[1];
    const float* c0    = (const float*)d_in[2];
    const float* Wih   = (const float*)d_in[3];
    const float* Whh   = (const float*)d_in[4];
    const float* bih   = (const float*)d_in[5];
    const float* bhh   = (const float*)d_in[6];
    float* out = (float*)d_out;

    constexpr int SMEM2 =
        (NQ_SM * G * 4 + H) * (int)sizeof(float) + H * (int)sizeof(float2);
    cudaFuncSetAttribute(lstm_kernel,
                         cudaFuncAttributeMaxDynamicSharedMemorySize, SMEM2);

    xproj_kernel<<<(B * T) / 32, 256>>>(input, Wih, bih, bhh);
    lstm_kernel<<<B, 256, SMEM2>>>(h0, c0, Whh, out);
}

// round 4
// speedup vs baseline: 1.5725x; 1.5725x over previous
#include <cuda_runtime.h>
#include <cstdint>
#include <cstddef>

// LSTM encoder: B=128, T=2048, I=64, H=128
// out[0 : B*H) = h_last ; out[B*H : ...) = encoded [B,T,H]
constexpr int B = 128;
constexpr int T = 2048;
constexpr int I = 64;
constexpr int H = 128;
constexpr int G = 4 * H;            // 512 gates
constexpr int KREG = 104;           // W_hh k-values in registers per gate
constexpr int NP   = KREG / 2;      // 52 f32x2 pairs per gate
constexpr int NQR  = KREG / 4;      // 26 register h-quads
constexpr int NQ_SM = (H - KREG) / 4; // 6 smem h-quads
constexpr int NQ   = NQR + NQ_SM;   // 32 total h-quads
constexpr int PF   = 4;             // h software-pipeline depth

__device__ float g_xp[(size_t)B * T * G + 2 * G];   // padded for overread

__device__ __forceinline__ void fma2(unsigned long long& d,
                                     unsigned long long a,
                                     unsigned long long b) {
    asm("fma.rn.f32x2 %0, %1, %2, %0;" : "+l"(d) : "l"(a), "l"(b));
}
__device__ __forceinline__ float pair_sum(unsigned long long v) {
    return __uint_as_float((unsigned)v) + __uint_as_float((unsigned)(v >> 32));
}
__device__ __forceinline__ float sig_f(float x) {
    return __fdividef(1.f, 1.f + __expf(-x));
}
__device__ __forceinline__ float tanh_f(float x) {
    return 1.f - 2.f * __fdividef(1.f, 1.f + __expf(2.f * x));
}

// ---------------------------------------------------------------------------
// x_proj (unchanged from R2): 256 threads, 32 rows/CTA, gates t and t+256.
// ---------------------------------------------------------------------------
__global__ void __launch_bounds__(256) xproj_kernel(
    const float* __restrict__ in,
    const float* __restrict__ Wih,
    const float* __restrict__ bih,
    const float* __restrict__ bhh)
{
    __shared__ float in_s[32 * I];
    const int t = threadIdx.x;
    const size_t row0 = (size_t)blockIdx.x * 32;

    {
        const float4* src = (const float4*)(in + row0 * I);
        float4* dst = (float4*)in_s;
        dst[t]       = src[t];
        dst[t + 256] = src[t + 256];
    }

    const int gA = t, gB = t + 256;
    unsigned long long wA[32], wB[32];
    {
        const unsigned long long* ra = (const unsigned long long*)(Wih + (size_t)gA * I);
        const unsigned long long* rb = (const unsigned long long*)(Wih + (size_t)gB * I);
#pragma unroll
        for (int i = 0; i < 32; i++) { wA[i] = ra[i]; wB[i] = rb[i]; }
    }
    const float biasA = bih[gA] + bhh[gA];
    const float biasB = bih[gB] + bhh[gB];
    __syncthreads();

    float* outp = g_xp + row0 * G + gA;
#pragma unroll 2
    for (int r = 0; r < 32; r++) {
        const ulonglong2* ip = (const ulonglong2*)(in_s + r * I);
        unsigned long long a0 = 0ull, a1 = 0ull, b0 = 0ull, b1 = 0ull;
#pragma unroll
        for (int q = 0; q < 16; q++) {
            ulonglong2 iv = ip[q];
            fma2(a0, wA[2 * q],     iv.x);
            fma2(a1, wA[2 * q + 1], iv.y);
            fma2(b0, wB[2 * q],     iv.x);
            fma2(b1, wB[2 * q + 1], iv.y);
        }
        outp[(size_t)r * G]       = pair_sum(a0) + pair_sum(a1) + biasA;
        outp[(size_t)r * G + 256] = pair_sum(b0) + pair_sum(b1) + biasB;
    }
}

// ---------------------------------------------------------------------------
// Recurrence: 1 CTA/batch row, 256 threads.
// Half A (tid<128, j=tid): rows j (i) and j+128 (f); owns c_j, does update.
// Half B (j=tid-128):      rows j+256 (g) and j+384 (o); sends (tanh g, sig o).
// Branchless activations via per-half constants; 4-deep h-LDS pipeline.
// ---------------------------------------------------------------------------
__global__ void __launch_bounds__(256, 1) lstm_kernel(
    const float* __restrict__ h0,
    const float* __restrict__ c0,
    const float* __restrict__ Whh,
    float* __restrict__ out)
{
    extern __shared__ float smem[];
    ulonglong2* Ws2  = (ulonglong2*)smem;            // [NQ_SM][G] quads, 48 KB
    float*      h_s  = smem + NQ_SM * G * 4;         // 128 floats
    float2*     ex_s = (float2*)(h_s + H);           // 128 float2

    const int tid  = threadIdx.x;
    const int half = tid >> 7;
    const int j    = tid & 127;
    const int g0   = (half << 8) + j;    // i (A) / g (B)
    const int g1   = g0 + 128;           // f (A) / o (B)
    const int b    = blockIdx.x;

    // activation constants: A: sigmoid  v0 = 1/(1+e^-x)
    //                       B: tanh     v0 = -2/(1+e^{2x}) + 1
    const float aa = half ? -2.f : 1.f;
    const float bb = half ?  2.f : -1.f;
    const float cc = half ?  1.f : 0.f;

    {   // smem weight slice, k in [KREG,128)
        const ulonglong2* r0 = (const ulonglong2*)(Whh + (size_t)g0 * H + KREG);
        const ulonglong2* r1 = (const ulonglong2*)(Whh + (size_t)g1 * H + KREG);
#pragma unroll
        for (int q = 0; q < NQ_SM; q++) {
            Ws2[q * G + g0] = r0[q];
            Ws2[q * G + g1] = r1[q];
        }
    }

    unsigned long long w0[NP], w1[NP];
    {
        const unsigned long long* r0 = (const unsigned long long*)(Whh + (size_t)g0 * H);
        const unsigned long long* r1 = (const unsigned long long*)(Whh + (size_t)g1 * H);
#pragma unroll
        for (int i = 0; i < NP; i++) { w0[i] = r0[i]; w1[i] = r1[i]; }
    }

    float c = 0.f, hn_last = 0.f;
    if (half == 0) {
        c = c0[b * H + j];
        h_s[j] = h0[b * H + j];
    }

    const float* xp = g_xp + (size_t)b * T * G + g0;  // g1 stream = +128
    float xc0 = xp[0], xc1 = xp[128];
    xp += G;

    __syncthreads();

    float* enc = out + (size_t)B * H + (size_t)b * T * H;

    for (int t = 0; t < T; t++) {
        // prefetch next step's x (distance-1; step length >> DRAM latency)
        float xn0 = xp[0], xn1 = xp[128];
        xp += G;

        unsigned long long a0 = 0ull, a1 = 0ull, b0 = 0ull, b1 = 0ull;
        const ulonglong2* h2 = (const ulonglong2*)h_s;

        ulonglong2 hbuf[PF];
#pragma unroll
        for (int q = 0; q < PF; q++) hbuf[q] = h2[q];

#pragma unroll
        for (int q = 0; q < NQ; q++) {
            ulonglong2 hv = hbuf[q & (PF - 1)];
            if (q + PF < NQ) hbuf[q & (PF - 1)] = h2[q + PF];
            if (q < NQR) {
                fma2(a0, w0[2 * q],     hv.x);
                fma2(a1, w0[2 * q + 1], hv.y);
                fma2(b0, w1[2 * q],     hv.x);
                fma2(b1, w1[2 * q + 1], hv.y);
            } else {
                ulonglong2 wa = Ws2[(q - NQR) * G + g0];
                ulonglong2 wb = Ws2[(q - NQR) * G + g1];
                fma2(a0, wa.x, hv.x);
                fma2(a1, wa.y, hv.y);
                fma2(b0, wb.x, hv.x);
                fma2(b1, wb.y, hv.y);
            }
        }

        float p0 = pair_sum(a0) + pair_sum(a1) + xc0;
        float p1 = pair_sum(b0) + pair_sum(b1) + xc1;
        xc0 = xn0; xc1 = xn1;

        // branchless per-half activations (identical instruction stream)
        float v0 = fmaf(aa, __fdividef(1.f, 1.f + __expf(bb * p0)), cc);
        float v1 = sig_f(p1);            // A: sig(f) ; B: sig(o)

        if (half) ex_s[j] = make_float2(v0, v1);
        __syncthreads();

        if (!half) {
            float2 go = ex_s[j];                 // (tanh g, sig o)
            c = v1 * c + v0 * go.x;              // sig(f)*c + sig(i)*tanh(g)
            float hn = go.y * tanh_f(c);
            h_s[j] = hn;
            enc[(size_t)t * H + j] = hn;
            hn_last = hn;
        }
        __syncthreads();
    }

    if (half == 0) out[b * H + j] = hn_last;
}

// ---------------------------------------------------------------------------
extern "C" void kernel_launch(void* const* d_in, const int* in_sizes, int n_in,
                              void* d_out, int out_size) {
    const float* input = (const float*)d_in[0];
    const float* h0    = (const float*)d_in[1];
    const float* c0    = (const float*)d_in[2];
    const float* Wih   = (const float*)d_in[3];
    const float* Whh   = (const float*)d_in[4];
    const float* bih   = (const float*)d_in[5];
    const float* bhh   = (const float*)d_in[6];
    float* out = (float*)d_out;

    constexpr int SMEM2 =
        (NQ_SM * G * 4 + H) * (int)sizeof(float) + H * (int)sizeof(float2);
    cudaFuncSetAttribute(lstm_kernel,
                         cudaFuncAttributeMaxDynamicSharedMemorySize, SMEM2);

    xproj_kernel<<<(B * T) / 32, 256>>>(input, Wih, bih, bhh);
    lstm_kernel<<<B, 256, SMEM2>>>(h0, c0, Whh, out);
}